// round 13
// baseline (speedup 1.0000x reference)
#include <cuda_runtime.h>
#include <cuda_bf16.h>

// Sinkhorn over [256, 512, 512], 10 iterations, T=1.
//
// Diagonal-scaling identity on K = exp(la0): r = 1/(K c), c = 1/(K^T r),
// out = exp(la0) * r c^T.  One fused pass over K per iteration.
//
// NEW: each batch is split across a 2-CTA cluster (256 rows per CTA) because
// the measured per-pass cost (~17-18 us regardless of inner loop) indicates a
// per-SM load-path floor (~4096 L1tex wavefronts/pass). Two SMs per tile
// halve it. Row dots are local; column partials are exchanged via DSMEM
// (st.shared::cluster into the peer's parity-double-buffered mailbox) with
// one cluster.sync per iteration.

#define BATCH 256
#define N     512
#define NITER 10
#define TPB   512
#define NWARP (TPB / 32)
#define ROWS_CTA 256                   // rows owned by each CTA (half batch)
#define RPW (ROWS_CTA / NWARP)         // 16 rows per warp
#define DYN_SMEM (92 * 1024)           // occupancy limiter: 1 CTA/SM

// 128 MB bf16 scratch for K (static __device__ array: no runtime allocation).
__device__ __nv_bfloat16 g_K[(size_t)BATCH * N * N];

// ---- cluster / DSMEM helpers ----
__device__ __forceinline__ unsigned ctarank() {
    unsigned r; asm("mov.u32 %0, %%cluster_ctarank;" : "=r"(r)); return r;
}
__device__ __forceinline__ unsigned mapa_peer(unsigned addr, unsigned rank) {
    unsigned r;
    asm("mapa.shared::cluster.u32 %0, %1, %2;" : "=r"(r) : "r"(addr), "r"(rank));
    return r;
}
__device__ __forceinline__ void st_cluster_f32(unsigned addr, float v) {
    asm volatile("st.shared::cluster.f32 [%0], %1;" :: "r"(addr), "f"(v) : "memory");
}
__device__ __forceinline__ void cluster_sync_() {
    asm volatile("barrier.cluster.arrive.aligned;" ::: "memory");
    asm volatile("barrier.cluster.wait.aligned;" ::: "memory");
}

// ---- bf16 / f32x2 helpers ----
__device__ __forceinline__ unsigned pack_bf2(float lo, float hi) {
    __nv_bfloat162 p = __floats2bfloat162_rn(lo, hi);
    return *reinterpret_cast<unsigned*>(&p);
}
__device__ __forceinline__ unsigned long long pk2(unsigned v) {
    unsigned lo = v << 16, hi = v & 0xffff0000u;
    unsigned long long p;
    asm("mov.b64 %0, {%1, %2};" : "=l"(p) : "r"(lo), "r"(hi));
    return p;
}
__device__ __forceinline__ unsigned long long fma2(unsigned long long a,
                                                   unsigned long long b,
                                                   unsigned long long c) {
    unsigned long long d;
    asm("fma.rn.f32x2 %0, %1, %2, %3;" : "=l"(d) : "l"(a), "l"(b), "l"(c));
    return d;
}
__device__ __forceinline__ float2 unpk2(unsigned long long p) {
    unsigned a, b;
    asm("mov.b64 {%0, %1}, %2;" : "=r"(a), "=r"(b) : "l"(p));
    return make_float2(__uint_as_float(a), __uint_as_float(b));
}
__device__ __forceinline__ void pack8(uint4 d0, uint4 d1, unsigned long long* k2) {
    k2[0] = pk2(d0.x); k2[1] = pk2(d0.y); k2[2] = pk2(d0.z); k2[3] = pk2(d0.w);
    k2[4] = pk2(d1.x); k2[5] = pk2(d1.y); k2[6] = pk2(d1.z); k2[7] = pk2(d1.w);
}

// One row: dot(k, c) -> butterfly reduce -> r -> r_own[i]; colacc += r * k.
__device__ __forceinline__ void proc_row(const unsigned long long* k2,
                                         const unsigned long long* cp,
                                         unsigned long long* colacc2,
                                         float* r_own, int i, int lane) {
    unsigned long long a0 = 0ull, a1 = 0ull;
    #pragma unroll
    for (int m = 0; m < 8; m += 2) {
        a0 = fma2(k2[m],     cp[m],     a0);
        a1 = fma2(k2[m + 1], cp[m + 1], a1);
    }
    float2 s0 = unpk2(a0), s1 = unpk2(a1);
    float acc = (s0.x + s0.y) + (s1.x + s1.y);
    #pragma unroll
    for (int off = 16; off > 0; off >>= 1)
        acc += __shfl_xor_sync(0xffffffffu, acc, off);
    float r = __frcp_rn(acc);
    if (lane == 0) r_own[i] = r;
    unsigned long long r2;
    unsigned ru = __float_as_uint(r);
    asm("mov.b64 %0, {%1, %1};" : "=l"(r2) : "r"(ru));
    #pragma unroll
    for (int m = 0; m < 8; m++) colacc2[m] = fma2(k2[m], r2, colacc2[m]);
}

__global__ __launch_bounds__(TPB, 1) __cluster_dims__(2, 1, 1)
void sinkhorn_kernel(const float* __restrict__ la, float* __restrict__ out) {
    __shared__ float r_own[ROWS_CTA];
    __shared__ float c_s[N];
    __shared__ float part[NWARP][N];   // per-warp column partials (32 KB)
    __shared__ float mb[2][N];         // peer mailbox, parity double-buffered

    const int tid  = threadIdx.x;
    const int warp = tid >> 5;
    const int lane = tid & 31;
    const unsigned rank = ctarank();
    const int batch = blockIdx.x >> 1;
    const size_t base = (size_t)batch * (size_t)(N * N) + (size_t)rank * ROWS_CTA * N;

    const float*   la_c = la + base;     // my 256 rows of this batch
    __nv_bfloat16* K_c  = g_K + base;

    // Safety: both cluster CTAs alive before any DSMEM traffic.
    cluster_sync_();

    // Per-iteration column-partial exchange: write my partial into the peer's
    // mailbox, cluster-sync (arrive=release orders the remote store), combine.
    const unsigned my_mb0  = (unsigned)__cvta_generic_to_shared(&mb[0][tid]);
    const unsigned my_mb1  = (unsigned)__cvta_generic_to_shared(&mb[1][tid]);
    const unsigned peer_mb0 = mapa_peer(my_mb0, rank ^ 1u);
    const unsigned peer_mb1 = mapa_peer(my_mb1, rank ^ 1u);

    // ================= Iteration 0, fused with K construction (c == 1) ======
    {
        float colacc[16];
        #pragma unroll
        for (int m = 0; m < 16; m++) colacc[m] = 0.f;

        for (int ri = 0; ri < RPW; ri++) {
            const int i = warp + ri * NWARP;            // local row 0..255
            const float4* lar = (const float4*)(la_c + (size_t)i * N);
            float4 a0 = lar[2 * lane];
            float4 a1 = lar[2 * lane + 1];
            float4 b0 = lar[64 + 2 * lane];
            float4 b1 = lar[64 + 2 * lane + 1];
            float f[16];
            f[0]  = __expf(a0.x); f[1]  = __expf(a0.y);
            f[2]  = __expf(a0.z); f[3]  = __expf(a0.w);
            f[4]  = __expf(a1.x); f[5]  = __expf(a1.y);
            f[6]  = __expf(a1.z); f[7]  = __expf(a1.w);
            f[8]  = __expf(b0.x); f[9]  = __expf(b0.y);
            f[10] = __expf(b0.z); f[11] = __expf(b0.w);
            f[12] = __expf(b1.x); f[13] = __expf(b1.y);
            f[14] = __expf(b1.z); f[15] = __expf(b1.w);

            uint4 d0, d1;
            d0.x = pack_bf2(f[0],  f[1]);  d0.y = pack_bf2(f[2],  f[3]);
            d0.z = pack_bf2(f[4],  f[5]);  d0.w = pack_bf2(f[6],  f[7]);
            d1.x = pack_bf2(f[8],  f[9]);  d1.y = pack_bf2(f[10], f[11]);
            d1.z = pack_bf2(f[12], f[13]); d1.w = pack_bf2(f[14], f[15]);
            uint4* Kr = (uint4*)(K_c + (size_t)i * N);
            Kr[lane]      = d0;
            Kr[32 + lane] = d1;

            float acc = (((f[0]+f[1])+(f[2]+f[3])) + ((f[4]+f[5])+(f[6]+f[7])))
                      + (((f[8]+f[9])+(f[10]+f[11])) + ((f[12]+f[13])+(f[14]+f[15])));
            #pragma unroll
            for (int off = 16; off > 0; off >>= 1)
                acc += __shfl_xor_sync(0xffffffffu, acc, off);
            float r = __frcp_rn(acc);
            if (lane == 0) r_own[i] = r;
            #pragma unroll
            for (int m = 0; m < 16; m++) colacc[m] = fmaf(r, f[m], colacc[m]);
        }
        *(float4*)&part[warp][8*lane]         = make_float4(colacc[0],  colacc[1],  colacc[2],  colacc[3]);
        *(float4*)&part[warp][8*lane + 4]     = make_float4(colacc[4],  colacc[5],  colacc[6],  colacc[7]);
        *(float4*)&part[warp][256 + 8*lane]   = make_float4(colacc[8],  colacc[9],  colacc[10], colacc[11]);
        *(float4*)&part[warp][256 + 8*lane+4] = make_float4(colacc[12], colacc[13], colacc[14], colacc[15]);
        __syncthreads();
        float Pown = 0.f;
        #pragma unroll
        for (int w = 0; w < NWARP; w++) Pown += part[w][tid];
        st_cluster_f32(peer_mb0, Pown);            // parity 0
        cluster_sync_();
        c_s[tid] = __frcp_rn(Pown + mb[0][tid]);
        __syncthreads();
    }

    // ===== Iterations 1..9: one pass over my 256 rows, depth-2 prefetch =====
    for (int t = 1; t < NITER; t++) {
        unsigned long long colacc2[8];
        #pragma unroll
        for (int m = 0; m < 8; m++) colacc2[m] = 0ull;

        unsigned long long cp[8];
        #pragma unroll
        for (int m = 0; m < 4; m++) {
            cp[m]     = *(const unsigned long long*)(c_s + 8 * lane + 2 * m);
            cp[4 + m] = *(const unsigned long long*)(c_s + 256 + 8 * lane + 2 * m);
        }

        uint4 A0, A1, B0, B1;
        {
            const uint4* P0 = (const uint4*)(K_c + (size_t)warp * N);
            A0 = P0[lane]; A1 = P0[32 + lane];
            const uint4* P1 = (const uint4*)(K_c + (size_t)(warp + NWARP) * N);
            B0 = P1[lane]; B1 = P1[32 + lane];
        }

        for (int ri = 0; ri < RPW; ri += 2) {
            unsigned long long k2a[8];
            pack8(A0, A1, k2a);
            {
                int nr = (ri + 2 < RPW) ? ri + 2 : RPW - 1;
                const uint4* P = (const uint4*)(K_c + (size_t)(warp + nr * NWARP) * N);
                A0 = P[lane]; A1 = P[32 + lane];
            }
            proc_row(k2a, cp, colacc2, r_own, warp + ri * NWARP, lane);

            unsigned long long k2b[8];
            pack8(B0, B1, k2b);
            {
                int nr = (ri + 3 < RPW) ? ri + 3 : RPW - 1;
                const uint4* P = (const uint4*)(K_c + (size_t)(warp + nr * NWARP) * N);
                B0 = P[lane]; B1 = P[32 + lane];
            }
            proc_row(k2b, cp, colacc2, r_own, warp + (ri + 1) * NWARP, lane);
        }

        {
            float2 t0 = unpk2(colacc2[0]), t1 = unpk2(colacc2[1]);
            float2 t2 = unpk2(colacc2[2]), t3 = unpk2(colacc2[3]);
            float2 t4 = unpk2(colacc2[4]), t5 = unpk2(colacc2[5]);
            float2 t6 = unpk2(colacc2[6]), t7 = unpk2(colacc2[7]);
            *(float4*)&part[warp][8*lane]         = make_float4(t0.x, t0.y, t1.x, t1.y);
            *(float4*)&part[warp][8*lane + 4]     = make_float4(t2.x, t2.y, t3.x, t3.y);
            *(float4*)&part[warp][256 + 8*lane]   = make_float4(t4.x, t4.y, t5.x, t5.y);
            *(float4*)&part[warp][256 + 8*lane+4] = make_float4(t6.x, t6.y, t7.x, t7.y);
        }
        __syncthreads();
        float Pown = 0.f;
        #pragma unroll
        for (int w = 0; w < NWARP; w++) Pown += part[w][tid];
        const int par = t & 1;
        st_cluster_f32(par ? peer_mb1 : peer_mb0, Pown);
        cluster_sync_();
        c_s[tid] = __frcp_rn(Pown + mb[par][tid]);
        __syncthreads();
    }

    // ================= Output: out = exp(la) * r_i * c_j (fp32 path) ========
    const float4* la4  = (const float4*)la_c;
    float4*       out4 = (float4*)(out + base);
    #pragma unroll 8
    for (int idx = tid; idx < (ROWS_CTA * N) / 4; idx += TPB) {
        float4 v = la4[idx];
        int i = idx >> 7;               // local row
        int j = (idx * 4) & (N - 1);
        float  ri = r_own[i];
        float4 cj = *(const float4*)(c_s + j);
        float4 o;
        o.x = __expf(v.x) * ri * cj.x;
        o.y = __expf(v.y) * ri * cj.y;
        o.z = __expf(v.z) * ri * cj.z;
        o.w = __expf(v.w) * ri * cj.w;
        out4[idx] = o;
    }
}

extern "C" void kernel_launch(void* const* d_in, const int* in_sizes, int n_in,
                              void* d_out, int out_size) {
    const float* la  = (const float*)d_in[0];
    float*       out = (float*)d_out;
    cudaFuncSetAttribute(sinkhorn_kernel,
                         cudaFuncAttributeMaxDynamicSharedMemorySize, DYN_SMEM);
    sinkhorn_kernel<<<2 * BATCH, TPB, DYN_SMEM>>>(la, out);
}